// round 3
// baseline (speedup 1.0000x reference)
#include <cuda_runtime.h>
#include <cuda_bf16.h>

// out[b,s,e] = W_e[e, tokens[b,s]] + W_p[s,e]
// tokens: (2,2048) int32, W_e: (1024,32000) f32, W_p: (2048,1024) f32
// out: (2,2048,1024) f32
//
// e-chunk-major schedule (4 chunks of 256 e-rows): bounds the W_e gather
// working set to ~28MB/chunk so duplicate token granules dedup in L2.
// Each thread: 1 token x 8 consecutive e-rows -> 8 independent L2-only
// gather loads in flight (deep MLP), coalesced W_p loads + streaming stores.

#define B 2
#define S 2048
#define E 1024
#define V 32000

#define NCHUNK 4          // 4 chunks x 256 e-rows
#define TOK_PER_BLK 8     // 8 warps = 8 tokens per block
#define GROUPS 512        // 4096 tokens / 8

__global__ __launch_bounds__(256, 8)
void embedding_gather_kernel(const int* __restrict__ tokens,
                             const float* __restrict__ W_e,
                             const float* __restrict__ W_p,
                             float* __restrict__ out) {
    int group = blockIdx.x & (GROUPS - 1);   // token-group: fast axis
    int chunk = blockIdx.x >> 9;             // e-chunk:     slow axis

    int t    = threadIdx.x;
    int lane = t & 31;                       // 32 lanes -> 256 e-rows (8 each)
    int w    = t >> 5;                       // warp -> token (warp-uniform)

    int tok = group * TOK_PER_BLK + w;       // bs in [0, 4096)
    int s   = tok & (S - 1);
    int e0  = chunk * 256 + lane * 8;        // first of 8 consecutive e-rows

    int v = __ldg(&tokens[tok]);             // warp-uniform broadcast

    // 8 independent column-gather loads, stride V (layout-forced scatter).
    // L2-only (cg): these lines have zero L1 reuse; don't thrash L1.
    const float* col = W_e + (size_t)e0 * V + v;
    float a0 = __ldcg(col);
    float a1 = __ldcg(col + 1 * V);
    float a2 = __ldcg(col + 2 * V);
    float a3 = __ldcg(col + 3 * V);
    float a4 = __ldcg(col + 4 * V);
    float a5 = __ldcg(col + 5 * V);
    float a6 = __ldcg(col + 6 * V);
    float a7 = __ldcg(col + 7 * V);

    // Positional add: two coalesced float4 loads.
    const float4* pp = reinterpret_cast<const float4*>(W_p + (size_t)s * E + e0);
    float4 p0 = __ldg(pp);
    float4 p1 = __ldg(pp + 1);

    float4 r0, r1;
    r0.x = a0 + p0.x;  r0.y = a1 + p0.y;  r0.z = a2 + p0.z;  r0.w = a3 + p0.w;
    r1.x = a4 + p1.x;  r1.y = a5 + p1.y;  r1.z = a6 + p1.z;  r1.w = a7 + p1.w;

    // Streaming stores: keep the 16MB output out of the gather working set.
    float4* op = reinterpret_cast<float4*>(out + (size_t)tok * E + e0);
    __stcs(op, r0);
    __stcs(op + 1, r1);
}

extern "C" void kernel_launch(void* const* d_in, const int* in_sizes, int n_in,
                              void* d_out, int out_size) {
    const int*   tokens = (const int*)d_in[0];
    const float* W_e    = (const float*)d_in[1];
    const float* W_p    = (const float*)d_in[2];
    float*       out    = (float*)d_out;

    // 2048 blocks x 256 threads; each thread emits 8 floats.
    embedding_gather_kernel<<<NCHUNK * GROUPS, 256>>>(tokens, W_e, W_p, out);
}

// round 4
// speedup vs baseline: 1.0560x; 1.0560x over previous
#include <cuda_runtime.h>
#include <cuda_bf16.h>

// out[b,s,e] = W_e[e, tokens[b,s]] + W_p[s,e]
// tokens: (2,2048) int32, W_e: (1024,32000) f32, W_p: (2048,1024) f32
// out: (2,2048,1024) f32
//
// The gather along a W_e column has stride V floats -> every lane a distinct
// 128B line. A 32-distinct-line LDG is serviced at the within-LDG replay rate
// (~2.07 cyc/wavefront), which is the measured bottleneck. Here each gather
// LDG uses 4-lane replica groups (4 lanes load the SAME address -> 1
// wavefront), so each LDG touches only 8 distinct lines; wavefronts become
// mostly cross-instruction (~1.0 cyc/wf), pushing the kernel back to the
// DRAM floor. A shuffle+select redistributes values so lane l holds e-row
// e_g + l for coalesced epilogue.
//
// e-chunk-major grid (4 chunks x 256 e-rows) kept from R2: bounds the L2
// working set so duplicate-token granules dedup (traffic floor ~150MB).

#define B 2
#define S 2048
#define E 1024
#define V 32000

#define NCHUNK 4
#define TOK_PER_BLK 8     // 8 warps = 8 tokens per block
#define GROUPS 512        // 4096 tokens / 8

__global__ __launch_bounds__(256)
void embedding_gather_kernel(const int* __restrict__ tokens,
                             const float* __restrict__ W_e,
                             const float* __restrict__ W_p,
                             float* __restrict__ out) {
    int group = blockIdx.x & (GROUPS - 1);   // token-group: fast axis
    int chunk = blockIdx.x >> 9;             // e-chunk:     slow axis

    int t    = threadIdx.x;
    int lane = t & 31;
    int w    = t >> 5;                       // warp -> token (warp-uniform)

    int tok = group * TOK_PER_BLK + w;       // bs in [0, 4096)
    int s   = tok & (S - 1);
    int e_c = chunk * 256;                   // chunk base e-row

    int v = __ldg(&tokens[tok]);             // warp-uniform broadcast

    const float* base = W_e + v;
    int e_rep = lane >> 2;                   // 0..7: this lane's replica e-sub

    // ---- Front-batched gather: 32 LDGs, each 8 distinct lines (4-lane
    //      replicas), all independent -> deep MLP, cross-LDG wavefronts.
    float a[8][4];
#pragma unroll
    for (int g = 0; g < 8; g++) {
#pragma unroll
        for (int i = 0; i < 4; i++) {
            int e = e_c + g * 32 + i * 8 + e_rep;
            a[g][i] = __ldcg(base + (size_t)e * V);
        }
    }

    // ---- Redistribute: after shuffles, lane l holds e-row (e_c + g*32 + l).
    //      Source for lane l is lane 4*(l&7), which loaded e-sub (l&7);
    //      keep iteration i == (l>>3).
    int src  = 4 * (lane & 7);
    int keep = lane >> 3;

#pragma unroll
    for (int g = 0; g < 8; g++) {
        float val = 0.0f;
#pragma unroll
        for (int i = 0; i < 4; i++) {
            float tv = __shfl_sync(0xffffffffu, a[g][i], src);
            if (keep == i) val = tv;
        }
        int e = e_c + g * 32 + lane;
        float p = __ldg(W_p + (size_t)s * E + e);
        __stcs(out + (size_t)tok * E + e, val + p);
    }
}

extern "C" void kernel_launch(void* const* d_in, const int* in_sizes, int n_in,
                              void* d_out, int out_size) {
    const int*   tokens = (const int*)d_in[0];
    const float* W_e    = (const float*)d_in[1];
    const float* W_p    = (const float*)d_in[2];
    float*       out    = (float*)d_out;

    embedding_gather_kernel<<<NCHUNK * GROUPS, 256>>>(tokens, W_e, W_p, out);
}